// round 15
// baseline (speedup 1.0000x reference)
#include <cuda_runtime.h>
#include <cstddef>

#define BATCH 16
#define NVERT 250000
#define NFACE 500000
#define MAXD  64                  // max adjacency entries per vertex (r8-proven)

// ---------------------------------------------------------------------------
// Device scratch (static; no runtime allocation allowed).
// g_deg starts zero-initialized (static storage); the gather kernel resets it
// to zero after use, so every kernel_launch sees zeroed degrees.
// ---------------------------------------------------------------------------
__device__ int   g_deg[NVERT];
// Fixed-stride adjacency: row v at g_adjf[v*MAXD], 256B-aligned rows
__device__ __align__(256) int g_adjf[(size_t)NVERT * MAXD];           // 64 MB
// [v][48]: b0(x,y,z) ... b15(x,y,z). 192B rows.
__device__ __align__(256) float g_vert3[(size_t)NVERT * BATCH * 3];   // 48 MB
// gather output staged [v][b] for coalesced writes, 16 MB
__device__ float g_outvb[(size_t)NVERT * BATCH];

// ---------------------------------------------------------------------------
// 1. FUSED prep kernel: grid-partitioned fill + transpose.
//    Blocks [0, FBLKS) build the adjacency (the long pole -> scheduled first);
//    blocks [FBLKS, FBLKS+TBLKS) transpose vert [B][N][3] -> g_vert3 [N][48].
//    Disjoint data; orthogonal bottlenecks (L2-atomic latency vs DRAM stream).
// ---------------------------------------------------------------------------
#define TVERTS 32
#define TBLKS ((NVERT + TVERTS - 1) / TVERTS)      // 7813
#define FBLKS ((NFACE + 255) / 256)                // 1954

__global__ void __launch_bounds__(256)
prep_kernel(const float* __restrict__ vert, const int* __restrict__ faces) {
    if (blockIdx.x < FBLKS) {
        // ---- fill part (fused count+fill; slots even -> aligned int2) ----
        int f = blockIdx.x * blockDim.x + threadIdx.x;
        if (f >= NFACE) return;
        int a = __ldg(&faces[3 * f + 0]);
        int b = __ldg(&faces[3 * f + 1]);
        int c = __ldg(&faces[3 * f + 2]);

        int pa = atomicAdd(&g_deg[a], 2);
        *reinterpret_cast<int2*>(&g_adjf[(size_t)a * MAXD + pa]) = make_int2(b, c);
        int pb = atomicAdd(&g_deg[b], 2);
        *reinterpret_cast<int2*>(&g_adjf[(size_t)b * MAXD + pb]) = make_int2(a, c);
        int pc = atomicAdd(&g_deg[c], 2);
        *reinterpret_cast<int2*>(&g_adjf[(size_t)c * MAXD + pc]) = make_int2(a, b);
    } else {
        // ---- transpose part ----
        __shared__ float sm[BATCH][TVERTS * 3 + 1];
        int v0 = (blockIdx.x - FBLKS) * TVERTS;
        int nv = NVERT - v0;
        if (nv > TVERTS) nv = TVERTS;
        int nfl = nv * 3;

        for (int i = threadIdx.x; i < BATCH * TVERTS * 3; i += 256) {
            int b = i / (TVERTS * 3);
            int r = i % (TVERTS * 3);
            if (r < nfl) {
                sm[b][r] = vert[((size_t)b * NVERT + v0) * 3 + r];
            }
        }
        __syncthreads();

        float* dst = g_vert3 + (size_t)v0 * (BATCH * 3);
        for (int i = threadIdx.x; i < nv * BATCH * 3; i += 256) {
            int vv = i / (BATCH * 3);
            int r = i % (BATCH * 3);
            int b = r / 3;
            int c = r % 3;
            dst[i] = sm[b][vv * 3 + c];
        }
    }
}

// ---------------------------------------------------------------------------
// 2. Gather + finalize: one warp per vertex, independent warps.
//    lane l: batch b = l&15, parity j = l>>4; half-warp per neighbor 192B row.
//    Inner loop unrolled x2: each parity lane consumes entries k, k+2 per
//    iteration, prefetching k+4, k+6 -> up to 12 row loads in flight per warp.
//    Resets g_deg[v] = 0 at the end (enables zero-kernel-free next call).
// ---------------------------------------------------------------------------
__global__ void __launch_bounds__(256)
gather_kernel() {
    int w = (blockIdx.x * blockDim.x + threadIdx.x) >> 5;
    if (w >= NVERT) return;
    int v = w;
    int lane = threadIdx.x & 31;
    int b = lane & 15;
    int j = lane >> 4;

    int d = g_deg[v];

    float ax = 0.f, ay = 0.f, az = 0.f;
    const int* __restrict__ adj = g_adjf + (size_t)v * MAXD;

    int k = j;
    int u0 = (k < d) ? __ldg(&adj[k]) : 0;
    int u1 = (k + 2 < d) ? __ldg(&adj[k + 2]) : 0;
    while (k < d) {
        int ka = k + 4;
        int kb = k + 6;
        int un0 = (ka < d) ? __ldg(&adj[ka]) : 0;   // prefetch next pair
        int un1 = (kb < d) ? __ldg(&adj[kb]) : 0;

        const float* __restrict__ p0 = g_vert3 + ((size_t)u0 * (BATCH * 3) + b * 3);
        float x0 = __ldg(&p0[0]), y0 = __ldg(&p0[1]), z0 = __ldg(&p0[2]);
        if (k + 2 < d) {
            const float* __restrict__ p1 = g_vert3 + ((size_t)u1 * (BATCH * 3) + b * 3);
            x0 += __ldg(&p1[0]);
            y0 += __ldg(&p1[1]);
            z0 += __ldg(&p1[2]);
        }
        ax += x0;
        ay += y0;
        az += z0;

        u0 = un0;
        u1 = un1;
        k = ka;
    }

    ax += __shfl_xor_sync(0xffffffffu, ax, 16);
    ay += __shfl_xor_sync(0xffffffffu, ay, 16);
    az += __shfl_xor_sync(0xffffffffu, az, 16);

    if (j == 0) {
        float inv = 1.0f / fmaxf((float)d, 1.0f);
        const float* __restrict__ p = g_vert3 + ((size_t)v * (BATCH * 3) + b * 3);
        float lx = ax * inv - p[0];
        float ly = ay * inv - p[1];
        float lz = az * inv - p[2];
        // coalesced: lanes 0..15 write 16 consecutive floats (64B run)
        g_outvb[(size_t)v * BATCH + b] = sqrtf(lx * lx + ly * ly + lz * lz);
    }

    // reset degree for the next kernel_launch call (statics start zeroed)
    if (lane == 0) g_deg[v] = 0;
}

// ---------------------------------------------------------------------------
// 3. Output transpose: g_outvb [N][B] -> out [B][N], both sides coalesced.
// ---------------------------------------------------------------------------
#define OVERTS 64
__global__ void __launch_bounds__(256)
out_transpose_kernel(float* __restrict__ out) {
    __shared__ float sm[OVERTS][BATCH + 1];
    int v0 = blockIdx.x * OVERTS;
    int nv = NVERT - v0;
    if (nv > OVERTS) nv = OVERTS;

    for (int i = threadIdx.x; i < nv * BATCH; i += 256) {
        int vv = i >> 4;
        int b = i & 15;
        sm[vv][b] = g_outvb[(size_t)(v0 + vv) * BATCH + b];
    }
    __syncthreads();

    for (int i = threadIdx.x; i < BATCH * OVERTS; i += 256) {
        int b = i >> 6;
        int vv = i & 63;
        if (vv < nv) {
            out[(size_t)b * NVERT + (v0 + vv)] = sm[vv][b];
        }
    }
}

// ---------------------------------------------------------------------------
extern "C" void kernel_launch(void* const* d_in, const int* in_sizes, int n_in,
                              void* d_out, int out_size) {
    const float* vert = (const float*)d_in[0];
    const int* faces = (const int*)d_in[1];
    float* out = (float*)d_out;

    const int T = 256;

    // fused fill + transpose (fill first: it's the long pole)
    prep_kernel<<<FBLKS + TBLKS, T>>>(vert, faces);

    {
        int warps_per_block = T / 32;  // 8
        int blocks = (NVERT + warps_per_block - 1) / warps_per_block;
        gather_kernel<<<blocks, T>>>();
    }

    out_transpose_kernel<<<(NVERT + OVERTS - 1) / OVERTS, T>>>(out);
}

// round 16
// speedup vs baseline: 1.0059x; 1.0059x over previous
#include <cuda_runtime.h>
#include <cstddef>

#define BATCH 16
#define NVERT 250000
#define NFACE 500000
#define MAXD  64                  // max adjacency entries per vertex (r8-proven)

// ---------------------------------------------------------------------------
// Device scratch (static; no runtime allocation allowed).
// g_deg starts zero-initialized (static storage); the gather kernel resets it
// to zero after use, so every kernel_launch sees zeroed degrees.
// ---------------------------------------------------------------------------
__device__ int   g_deg[NVERT];
// Fixed-stride adjacency: row v at g_adjf[v*MAXD], 256B-aligned rows
__device__ __align__(256) int g_adjf[(size_t)NVERT * MAXD];           // 64 MB
// [v][48]: b0(x,y,z) ... b15(x,y,z). 192B rows.
__device__ __align__(256) float g_vert3[(size_t)NVERT * BATCH * 3];   // 48 MB
// gather output staged [v][b] for coalesced writes, 16 MB
__device__ float g_outvb[(size_t)NVERT * BATCH];

// ---------------------------------------------------------------------------
// 1. FUSED prep kernel: grid-partitioned transpose + fill (r14-proven order).
//    Blocks [0, TBLKS) transpose vert [B][N][3] -> g_vert3 [N][48];
//    blocks [TBLKS, TBLKS+FBLKS) build the adjacency.
//    Fill issues all three atomics before the dependent stores (MLP=3 on the
//    318-cycle ATOMG chains instead of serialized).
// ---------------------------------------------------------------------------
#define TVERTS 32
#define TBLKS ((NVERT + TVERTS - 1) / TVERTS)      // 7813
#define FBLKS ((NFACE + 255) / 256)                // 1954

__global__ void __launch_bounds__(256)
prep_kernel(const float* __restrict__ vert, const int* __restrict__ faces) {
    if (blockIdx.x < TBLKS) {
        // ---- transpose part ----
        __shared__ float sm[BATCH][TVERTS * 3 + 1];
        int v0 = blockIdx.x * TVERTS;
        int nv = NVERT - v0;
        if (nv > TVERTS) nv = TVERTS;
        int nfl = nv * 3;

        for (int i = threadIdx.x; i < BATCH * TVERTS * 3; i += 256) {
            int b = i / (TVERTS * 3);
            int r = i % (TVERTS * 3);
            if (r < nfl) {
                sm[b][r] = vert[((size_t)b * NVERT + v0) * 3 + r];
            }
        }
        __syncthreads();

        float* dst = g_vert3 + (size_t)v0 * (BATCH * 3);
        for (int i = threadIdx.x; i < nv * BATCH * 3; i += 256) {
            int vv = i / (BATCH * 3);
            int r = i % (BATCH * 3);
            int b = r / 3;
            int c = r % 3;
            dst[i] = sm[b][vv * 3 + c];
        }
    } else {
        // ---- fill part ----
        int f = (blockIdx.x - TBLKS) * blockDim.x + threadIdx.x;
        if (f >= NFACE) return;
        int a = __ldg(&faces[3 * f + 0]);
        int b = __ldg(&faces[3 * f + 1]);
        int c = __ldg(&faces[3 * f + 2]);

        // all three atomics in flight before any dependent store
        int pa = atomicAdd(&g_deg[a], 2);
        int pb = atomicAdd(&g_deg[b], 2);
        int pc = atomicAdd(&g_deg[c], 2);
        *reinterpret_cast<int2*>(&g_adjf[(size_t)a * MAXD + pa]) = make_int2(b, c);
        *reinterpret_cast<int2*>(&g_adjf[(size_t)b * MAXD + pb]) = make_int2(a, c);
        *reinterpret_cast<int2*>(&g_adjf[(size_t)c * MAXD + pc]) = make_int2(a, b);
    }
}

// ---------------------------------------------------------------------------
// 2. Gather + finalize (exact r8 loop): one warp per vertex, independent
//    warps. lane l: batch b = l&15, parity j = l>>4; half-warp per neighbor
//    192B row, adjacency prefetched one iteration ahead.
//    Resets g_deg[v] = 0 at the end (zero-kernel-free next call).
// ---------------------------------------------------------------------------
__global__ void __launch_bounds__(256)
gather_kernel() {
    int w = (blockIdx.x * blockDim.x + threadIdx.x) >> 5;
    if (w >= NVERT) return;
    int v = w;
    int lane = threadIdx.x & 31;
    int b = lane & 15;
    int j = lane >> 4;

    int d = g_deg[v];

    float ax = 0.f, ay = 0.f, az = 0.f;
    const int* __restrict__ adj = g_adjf + (size_t)v * MAXD;

    int k = j;
    int u = (k < d) ? __ldg(&adj[k]) : 0;
    while (k < d) {
        int k2 = k + 2;
        int u_next = (k2 < d) ? __ldg(&adj[k2]) : 0;   // prefetch: breaks chain
        const float* __restrict__ p = g_vert3 + ((size_t)u * (BATCH * 3) + b * 3);
        ax += __ldg(&p[0]);
        ay += __ldg(&p[1]);
        az += __ldg(&p[2]);
        u = u_next;
        k = k2;
    }

    ax += __shfl_xor_sync(0xffffffffu, ax, 16);
    ay += __shfl_xor_sync(0xffffffffu, ay, 16);
    az += __shfl_xor_sync(0xffffffffu, az, 16);

    if (j == 0) {
        float inv = 1.0f / fmaxf((float)d, 1.0f);
        const float* __restrict__ p = g_vert3 + ((size_t)v * (BATCH * 3) + b * 3);
        float lx = ax * inv - p[0];
        float ly = ay * inv - p[1];
        float lz = az * inv - p[2];
        // coalesced: lanes 0..15 write 16 consecutive floats (64B run)
        g_outvb[(size_t)v * BATCH + b] = sqrtf(lx * lx + ly * ly + lz * lz);
    }

    // reset degree for the next kernel_launch call (statics start zeroed)
    if (lane == 0) g_deg[v] = 0;
}

// ---------------------------------------------------------------------------
// 3. Output transpose: g_outvb [N][B] -> out [B][N], both sides coalesced.
// ---------------------------------------------------------------------------
#define OVERTS 64
__global__ void __launch_bounds__(256)
out_transpose_kernel(float* __restrict__ out) {
    __shared__ float sm[OVERTS][BATCH + 1];
    int v0 = blockIdx.x * OVERTS;
    int nv = NVERT - v0;
    if (nv > OVERTS) nv = OVERTS;

    for (int i = threadIdx.x; i < nv * BATCH; i += 256) {
        int vv = i >> 4;
        int b = i & 15;
        sm[vv][b] = g_outvb[(size_t)(v0 + vv) * BATCH + b];
    }
    __syncthreads();

    for (int i = threadIdx.x; i < BATCH * OVERTS; i += 256) {
        int b = i >> 6;
        int vv = i & 63;
        if (vv < nv) {
            out[(size_t)b * NVERT + (v0 + vv)] = sm[vv][b];
        }
    }
}

// ---------------------------------------------------------------------------
extern "C" void kernel_launch(void* const* d_in, const int* in_sizes, int n_in,
                              void* d_out, int out_size) {
    const float* vert = (const float*)d_in[0];
    const int* faces = (const int*)d_in[1];
    float* out = (float*)d_out;

    const int T = 256;

    // fused transpose + adjacency build (independent halves overlap)
    prep_kernel<<<TBLKS + FBLKS, T>>>(vert, faces);

    {
        int warps_per_block = T / 32;  // 8
        int blocks = (NVERT + warps_per_block - 1) / warps_per_block;
        gather_kernel<<<blocks, T>>>();
    }

    out_transpose_kernel<<<(NVERT + OVERTS - 1) / OVERTS, T>>>(out);
}

// round 17
// speedup vs baseline: 1.0859x; 1.0795x over previous
#include <cuda_runtime.h>
#include <cstddef>

#define BATCH 16
#define NVERT 250000
#define NFACE 500000
#define MAXD  64                  // max adjacency entries per vertex (r8-proven)

// ---------------------------------------------------------------------------
// Device scratch (static; no runtime allocation allowed).
// g_deg starts zero-initialized (static storage); the gather kernel resets it
// to zero after use, so every kernel_launch sees zeroed degrees.
// ---------------------------------------------------------------------------
__device__ int   g_deg[NVERT];
// Fixed-stride adjacency: row v at g_adjf[v*MAXD], 256B-aligned rows
__device__ __align__(256) int g_adjf[(size_t)NVERT * MAXD];           // 64 MB
// [v][48]: b0(x,y,z) ... b15(x,y,z). 192B rows.
__device__ __align__(256) float g_vert3[(size_t)NVERT * BATCH * 3];   // 48 MB
// gather output staged [v][b] for coalesced writes, 16 MB
__device__ float g_outvb[(size_t)NVERT * BATCH];

// ---------------------------------------------------------------------------
// 1. FUSED prep kernel with INTERLEAVED partitions: every 5th block is a
//    fill block, the rest transpose. Both sub-workloads occupy the chip from
//    wave 0 and overlap (fill = L2-atomic latency-bound, transpose =
//    DRAM-stream-bound).
//      fill:      bx % 5 == 0  -> f_block = bx / 5            (1954 blocks)
//      transpose: bx % 5 != 0  -> t_block = bx - bx/5 - 1     (7813 blocks)
// ---------------------------------------------------------------------------
#define TVERTS 32
#define TBLKS ((NVERT + TVERTS - 1) / TVERTS)      // 7813
#define FBLKS ((NFACE + 255) / 256)                // 1954
#define PBLKS (TBLKS + FBLKS)                      // 9767

__global__ void __launch_bounds__(256)
prep_kernel(const float* __restrict__ vert, const int* __restrict__ faces) {
    int bx = blockIdx.x;
    if (bx % 5 == 0) {
        // ---- fill part (fused count+fill; slots even -> aligned int2) ----
        int f = (bx / 5) * blockDim.x + threadIdx.x;
        if (f >= NFACE) return;
        int a = __ldg(&faces[3 * f + 0]);
        int b = __ldg(&faces[3 * f + 1]);
        int c = __ldg(&faces[3 * f + 2]);

        int pa = atomicAdd(&g_deg[a], 2);
        int pb = atomicAdd(&g_deg[b], 2);
        int pc = atomicAdd(&g_deg[c], 2);
        *reinterpret_cast<int2*>(&g_adjf[(size_t)a * MAXD + pa]) = make_int2(b, c);
        *reinterpret_cast<int2*>(&g_adjf[(size_t)b * MAXD + pb]) = make_int2(a, c);
        *reinterpret_cast<int2*>(&g_adjf[(size_t)c * MAXD + pc]) = make_int2(a, b);
    } else {
        // ---- transpose part ----
        __shared__ float sm[BATCH][TVERTS * 3 + 1];
        int tb = bx - bx / 5 - 1;
        int v0 = tb * TVERTS;
        int nv = NVERT - v0;
        if (nv > TVERTS) nv = TVERTS;
        int nfl = nv * 3;

        for (int i = threadIdx.x; i < BATCH * TVERTS * 3; i += 256) {
            int b = i / (TVERTS * 3);
            int r = i % (TVERTS * 3);
            if (r < nfl) {
                sm[b][r] = vert[((size_t)b * NVERT + v0) * 3 + r];
            }
        }
        __syncthreads();

        float* dst = g_vert3 + (size_t)v0 * (BATCH * 3);
        for (int i = threadIdx.x; i < nv * BATCH * 3; i += 256) {
            int vv = i / (BATCH * 3);
            int r = i % (BATCH * 3);
            int b = r / 3;
            int c = r % 3;
            dst[i] = sm[b][vv * 3 + c];
        }
    }
}

// ---------------------------------------------------------------------------
// 2. Gather + finalize (r8 loop): one warp per vertex, independent warps.
//    lane l: batch b = l&15, parity j = l>>4; half-warp per neighbor 192B
//    row, adjacency prefetched one iteration ahead.
//    Resets g_deg[v] = 0 at the end (zero-kernel-free next call).
// ---------------------------------------------------------------------------
__global__ void __launch_bounds__(256)
gather_kernel() {
    int w = (blockIdx.x * blockDim.x + threadIdx.x) >> 5;
    if (w >= NVERT) return;
    int v = w;
    int lane = threadIdx.x & 31;
    int b = lane & 15;
    int j = lane >> 4;

    int d = g_deg[v];

    float ax = 0.f, ay = 0.f, az = 0.f;
    const int* __restrict__ adj = g_adjf + (size_t)v * MAXD;

    int k = j;
    int u = (k < d) ? __ldg(&adj[k]) : 0;
    while (k < d) {
        int k2 = k + 2;
        int u_next = (k2 < d) ? __ldg(&adj[k2]) : 0;   // prefetch: breaks chain
        const float* __restrict__ p = g_vert3 + ((size_t)u * (BATCH * 3) + b * 3);
        ax += __ldg(&p[0]);
        ay += __ldg(&p[1]);
        az += __ldg(&p[2]);
        u = u_next;
        k = k2;
    }

    ax += __shfl_xor_sync(0xffffffffu, ax, 16);
    ay += __shfl_xor_sync(0xffffffffu, ay, 16);
    az += __shfl_xor_sync(0xffffffffu, az, 16);

    if (j == 0) {
        float inv = 1.0f / fmaxf((float)d, 1.0f);
        const float* __restrict__ p = g_vert3 + ((size_t)v * (BATCH * 3) + b * 3);
        float lx = ax * inv - p[0];
        float ly = ay * inv - p[1];
        float lz = az * inv - p[2];
        // coalesced: lanes 0..15 write 16 consecutive floats (64B run)
        g_outvb[(size_t)v * BATCH + b] = sqrtf(lx * lx + ly * ly + lz * lz);
    }

    // reset degree for the next kernel_launch call (statics start zeroed)
    if (lane == 0) g_deg[v] = 0;
}

// ---------------------------------------------------------------------------
// 3. Output transpose: g_outvb [N][B] -> out [B][N], both sides coalesced.
// ---------------------------------------------------------------------------
#define OVERTS 64
__global__ void __launch_bounds__(256)
out_transpose_kernel(float* __restrict__ out) {
    __shared__ float sm[OVERTS][BATCH + 1];
    int v0 = blockIdx.x * OVERTS;
    int nv = NVERT - v0;
    if (nv > OVERTS) nv = OVERTS;

    for (int i = threadIdx.x; i < nv * BATCH; i += 256) {
        int vv = i >> 4;
        int b = i & 15;
        sm[vv][b] = g_outvb[(size_t)(v0 + vv) * BATCH + b];
    }
    __syncthreads();

    for (int i = threadIdx.x; i < BATCH * OVERTS; i += 256) {
        int b = i >> 6;
        int vv = i & 63;
        if (vv < nv) {
            out[(size_t)b * NVERT + (v0 + vv)] = sm[vv][b];
        }
    }
}

// ---------------------------------------------------------------------------
extern "C" void kernel_launch(void* const* d_in, const int* in_sizes, int n_in,
                              void* d_out, int out_size) {
    const float* vert = (const float*)d_in[0];
    const int* faces = (const int*)d_in[1];
    float* out = (float*)d_out;

    const int T = 256;

    // fused transpose + adjacency build, block types interleaved 4:1
    prep_kernel<<<PBLKS, T>>>(vert, faces);

    {
        int warps_per_block = T / 32;  // 8
        int blocks = (NVERT + warps_per_block - 1) / warps_per_block;
        gather_kernel<<<blocks, T>>>();
    }

    out_transpose_kernel<<<(NVERT + OVERTS - 1) / OVERTS, T>>>(out);
}